// round 14
// baseline (speedup 1.0000x reference)
#include <cuda_runtime.h>
#include <math.h>
#include <stdint.h>

// Problem constants
#define NT 365
#define NS 300
#define NH 128
#define NG 32
#define NR 8
#define NROWS (NT*NS)          // 109500
#define KDIM 256
#define K2DIM 128              // bf16x2 words per row
#define NDIM 384               // NH*3
#define MTILE 128
#define NTILES ((NROWS + MTILE - 1)/MTILE)   // 856

// ---------------- scratch (device globals; no allocation in kernel_launch) --------
__device__ uint32_t g_Hh[NROWS*K2DIM];   // H hi bf16x2, [row][k2]
__device__ uint32_t g_Hl[NROWS*K2DIM];   // H lo bf16x2
__device__ uint32_t g_Wh[NDIM*K2DIM];    // W2 hi bf16x2, [n][k2]
__device__ uint32_t g_Wl[NDIM*K2DIM];    // W2 lo bf16x2
__device__ float g_Pl[NROWS*NH];         // rain per bucket
__device__ float g_Ev[NROWS*NH];         // evap per bucket
__device__ float g_vm[NROWS*NH];         // melt cap
__device__ float g_Ps [NROWS];           // snow precip (scalar per row)
__device__ float g_Plb[NROWS];           // P*(1-vf)
__device__ float g_cT[NS*KDIM];          // fcT layer1 static part [s][k] (incl b1)
__device__ float g_cc[NS*NDIM];          // fcCT static part (incl bias)
__device__ float g_gates[NS*6*NH];       // kp,ks,kg,gp,gL,qb
__device__ float g_rg[NS*NH*NR];         // relu(r) * ga  (ga folded into taps)
__device__ float g_pq[NROWS*4];          // per-warp partial sums of Q-conv
__device__ float g_pc[NROWS*4];          // per-warp partial sums of C-conv

// =============================== small helpers ====================================
__device__ __forceinline__ uint32_t pack_bf16(float lo, float hi) {
    uint32_t r; asm("cvt.rn.bf16x2.f32 %0, %1, %2;" : "=r"(r) : "f"(hi), "f"(lo));
    return r;
}
__device__ __forceinline__ void mma16n8k16bf(float* c, const uint32_t* a, const uint32_t* b) {
    asm volatile("mma.sync.aligned.m16n8k16.row.col.f32.bf16.bf16.f32 "
        "{%0,%1,%2,%3}, {%4,%5,%6,%7}, {%8,%9}, {%0,%1,%2,%3};"
        : "+f"(c[0]), "+f"(c[1]), "+f"(c[2]), "+f"(c[3])
        : "r"(a[0]), "r"(a[1]), "r"(a[2]), "r"(a[3]), "r"(b[0]), "r"(b[1]));
}
// split one float into (hi bf16-as-float, lo residual)
__device__ __forceinline__ void split2(float a, float b, uint32_t& ph, uint32_t& pl) {
    ph = pack_bf16(a, b);
    float r0 = a - __uint_as_float(ph << 16);
    float r1 = b - __uint_as_float(ph & 0xFFFF0000u);
    pl = pack_bf16(r0, r1);
}

// ======================= Kernel 1: per-site MLPs (fcW, fcR, statics) ==============
#define SB 6    // sites per block; 300/6 = 50 blocks
__global__ void __launch_bounds__(256) site_kernel(
    const float* __restrict__ xc,
    const float* __restrict__ fcR_w1, const float* __restrict__ fcR_b1,
    const float* __restrict__ fcR_w2, const float* __restrict__ fcR_b2,
    const float* __restrict__ fcW_w1, const float* __restrict__ fcW_b1,
    const float* __restrict__ fcW_w2, const float* __restrict__ fcW_b2,
    const float* __restrict__ fcT_w1, const float* __restrict__ fcT_b1,
    const float* __restrict__ fcCT_w, const float* __restrict__ fcCT_b)
{
    int s0  = blockIdx.x * SB;
    int tid = threadIdx.x;
    int lane = tid & 31, warp = tid >> 5;
    __shared__ float sxc[SB][32];
    __shared__ float hW [SB][257];
    __shared__ float hR [SB][257];
    __shared__ float sga[SB][128];

    for (int i = tid; i < SB*32; i += 256)
        sxc[i/32][i%32] = xc[(s0 + i/32)*32 + (i%32)];
    __syncthreads();

    {
        int k = tid;
        float aW[SB], aR[SB], aT[SB];
        #pragma unroll
        for (int s = 0; s < SB; s++) { aW[s]=0.f; aR[s]=0.f; aT[s]=0.f; }
        for (int j = 0; j < 32; j++) {
            float wW = fcW_w1[k*32 + j];
            float wR = fcR_w1[k*32 + j];
            float wT = fcT_w1[k*38 + 6 + j];
            #pragma unroll
            for (int s = 0; s < SB; s++) {
                float xv = sxc[s][j];
                aW[s] += wW*xv; aR[s] += wR*xv; aT[s] += wT*xv;
            }
        }
        float bW = fcW_b1[k], bR = fcR_b1[k], bT = fcT_b1[k];
        #pragma unroll
        for (int s = 0; s < SB; s++) {
            hW[s][k] = tanhf(aW[s] + bW);
            hR[s][k] = tanhf(aR[s] + bR);
            g_cT[(s0+s)*KDIM + k] = aT[s] + bT;
        }
    }
    for (int o = tid; o < NDIM; o += 256) {
        float acc[SB];
        float b = fcCT_b[o];
        #pragma unroll
        for (int s = 0; s < SB; s++) acc[s] = b;
        for (int j = 0; j < 32; j++) {
            float w = fcCT_w[o*34 + 2 + j];
            #pragma unroll
            for (int s = 0; s < SB; s++) acc[s] += w * sxc[s][j];
        }
        #pragma unroll
        for (int s = 0; s < SB; s++) g_cc[(s0+s)*NDIM + o] = acc[s];
    }
    __syncthreads();

    // fcW layer 2 -> gates: warp-per-output; lane covers k = j*32+lane, j=0..7
    for (int i = 0; i < 7*NH/8; i++) {
        int o = i*8 + warp;
        float w[8];
        #pragma unroll
        for (int j = 0; j < 8; j++) w[j] = fcW_w2[o*KDIM + j*32 + lane];
        float acc[SB];
        #pragma unroll
        for (int s = 0; s < SB; s++) {
            float a = 0.f;
            #pragma unroll
            for (int j = 0; j < 8; j++) a += w[j]*hW[s][j*32 + lane];
            acc[s] = a;
        }
        #pragma unroll
        for (int off = 16; off; off >>= 1)
            #pragma unroll
            for (int s = 0; s < SB; s++)
                acc[s] += __shfl_down_sync(0xffffffffu, acc[s], off);
        if (lane == 0) {
            float b = fcW_b2[o];
            int g = o >> 7, h = o & 127;
            #pragma unroll
            for (int s = 0; s < SB; s++) {
                float a = acc[s] + b;
                if      (g < 4)  g_gates[(s0+s)*6*NH + g*NH + h] = 1.f/(1.f + expf(-a));
                else if (g == 4) g_gates[(s0+s)*6*NH + 4*NH + h] = expf(a)*2.f;
                else if (g == 5) g_gates[(s0+s)*6*NH + 5*NH + h] = fmaxf(a, 0.f);
                else             sga[s][h] = a;
            }
        }
    }
    __syncthreads();

    if (tid < SB) {
        float m = -1e30f;
        for (int h = 0; h < NH; h++) m = fmaxf(m, sga[tid][h]);
        float sum = 0.f;
        for (int h = 0; h < NH; h++) { float e = expf(sga[tid][h] - m); sga[tid][h] = e; sum += e; }
        float inv = 1.f / sum;
        for (int h = 0; h < NH; h++) sga[tid][h] *= inv;
    }
    __syncthreads();

    for (int i = 0; i < NH*NR/8; i++) {
        int o = i*8 + warp;
        float w[8];
        #pragma unroll
        for (int j = 0; j < 8; j++) w[j] = fcR_w2[o*KDIM + j*32 + lane];
        float acc[SB];
        #pragma unroll
        for (int s = 0; s < SB; s++) {
            float a = 0.f;
            #pragma unroll
            for (int j = 0; j < 8; j++) a += w[j]*hR[s][j*32 + lane];
            acc[s] = a;
        }
        #pragma unroll
        for (int off = 16; off; off >>= 1)
            #pragma unroll
            for (int s = 0; s < SB; s++)
                acc[s] += __shfl_down_sync(0xffffffffu, acc[s], off);
        if (lane == 0) {
            float b = fcR_b2[o];
            int h = o >> 3;
            #pragma unroll
            for (int s = 0; s < SB; s++)
                g_rg[(s0+s)*NH*NR + o] = fmaxf(acc[s] + b, 0.f) * sga[s][h];
        }
    }
}

// ============== Kernel 1b: pre-split W2 into bf16 hi/lo (runs once) ===============
__global__ void __launch_bounds__(256) split_w_kernel(const float* __restrict__ W2)
{
    int idx = blockIdx.x*256 + threadIdx.x;    // n*K2DIM + k2
    if (idx >= NDIM*K2DIM) return;
    int n = idx >> 7, k2 = idx & 127;
    float2 v = *(const float2*)&W2[(size_t)n*KDIM + 2*k2];
    uint32_t ph, pl;
    split2(v.x, v.y, ph, pl);
    g_Wh[idx] = ph;
    g_Wl[idx] = pl;
}

// ====== Kernel 2a: fcT layer-1 tanh ONCE -> bf16 hi/lo pairs + snow split =========
__global__ void __launch_bounds__(128) hidden_kernel(
    const float* __restrict__ x, const float* __restrict__ fcT_w1)
{
    int rm = blockIdx.x;             // row = t*NS + s
    int k2 = threadIdx.x;            // 0..127
    int s  = rm % NS;
    const float* xr = x + (size_t)rm*6;
    int k0 = 2*k2;
    float acc0 = g_cT[s*KDIM + k0];
    float acc1 = g_cT[s*KDIM + k0 + 1];
    #pragma unroll
    for (int j = 0; j < 6; j++) {
        float xv = xr[j];
        acc0 += fcT_w1[k0*38 + j]     * xv;
        acc1 += fcT_w1[(k0+1)*38 + j] * xv;
    }
    float h0 = tanhf(acc0), h1 = tanhf(acc1);
    uint32_t ph, pl;
    split2(h0, h1, ph, pl);
    size_t o = (size_t)rm*K2DIM + k2;
    g_Hh[o] = ph;
    g_Hl[o] = pl;

    if (k2 == 0) {
        float P = xr[0], T1 = xr[2], T2 = xr[3];
        float d = T2 - T1;
        float ratio = (T1 + T2) / (d == 0.f ? 1.f : d);
        ratio = fminf(fmaxf(ratio, -1.f), 1.f);
        float vf = acosf(ratio) / 3.1415f;
        if (T1 >= 0.f) vf = 0.f;
        else if (T2 <= 0.f) vf = 1.f;
        g_Ps [rm] = P * vf;
        g_Plb[rm] = P * (1.f - vf);
    }
}

// ===== Kernel 2b: fcT layer-2, 3x-BF16 m16n8k16 mma.sync GEMM + fused epilogue ====
#define SA 136
#define SBN 72
#define AOFF_L (16*SA)
#define BOFF_H (2*16*SA)
#define BOFF_L (BOFF_H + 16*SBN)
#define SM_WORDS (BOFF_L + 16*SBN)
#define SM_BYTES (SM_WORDS*4)            // 26624

__global__ void __launch_bounds__(256)
fct_mma_kernel(const float* __restrict__ x, const float* __restrict__ b2)
{
    extern __shared__ uint32_t sm[];
    int tid  = threadIdx.x;
    int lane = tid & 31, wid = tid >> 5;
    int wm = (wid & 3) * 32;
    int wn = (wid >> 2) * 32;
    int grp = lane >> 2, tig = lane & 3;
    int rowBase = blockIdx.y * MTILE;
    int nBase   = blockIdx.x * 64;
    int g       = blockIdx.x >> 1;

    float acc[2][4][4];
    #pragma unroll
    for (int mt = 0; mt < 2; mt++)
        #pragma unroll
        for (int nt = 0; nt < 4; nt++)
            #pragma unroll
            for (int q = 0; q < 4; q++) acc[mt][nt][q] = 0.f;

    int ar   = tid >> 1;          // A-fill row 0..127
    int ahal = tid & 1;           // which 8-word half of the 16 k2 slice
    int rmA  = rowBase + ar;
    bool aok = rmA < NROWS;

    for (int chunk = 0; chunk < 8; chunk++) {
        int kb = chunk * 16;       // k2 base
        // ---- fill A: pure copy of pre-split pairs ----
        {
            size_t src = (size_t)rmA*K2DIM + kb + ahal*8;
            uint4 h0 = make_uint4(0,0,0,0), h1 = h0, l0 = h0, l1 = h0;
            if (aok) {
                h0 = *(const uint4*)&g_Hh[src];
                h1 = *(const uint4*)&g_Hh[src + 4];
                l0 = *(const uint4*)&g_Hl[src];
                l1 = *(const uint4*)&g_Hl[src + 4];
            }
            int kl = ahal*8;
            const uint32_t* hp = (const uint32_t*)&h0;
            const uint32_t* lp = (const uint32_t*)&l0;
            #pragma unroll
            for (int w = 0; w < 4; w++) {
                sm[(kl+w)*SA + ar]          = hp[w];
                sm[AOFF_L + (kl+w)*SA + ar] = lp[w];
            }
            hp = (const uint32_t*)&h1; lp = (const uint32_t*)&l1;
            #pragma unroll
            for (int w = 0; w < 4; w++) {
                sm[(kl+4+w)*SA + ar]          = hp[w];
                sm[AOFF_L + (kl+4+w)*SA + ar] = lp[w];
            }
        }
        // ---- fill B: pure copy of pre-split pairs ----
        #pragma unroll
        for (int i = 0; i < 4; i++) {
            int idx = tid + i*256;            // 1024 = 64 n x 16 k2
            int n = idx >> 4, k2l = idx & 15;
            size_t src = (size_t)(nBase + n)*K2DIM + kb + k2l;
            sm[BOFF_H + k2l*SBN + n] = g_Wh[src];
            sm[BOFF_L + k2l*SBN + n] = g_Wl[src];
        }
        __syncthreads();

        // ---- 2 k16-steps of mma ----
        #pragma unroll
        for (int ks = 0; ks < 2; ks++) {
            int k2r  = ks*8 + tig;
            int k2r4 = k2r + 4;
            uint32_t ah[2][4], al[2][4], bh[4][2], bl[4][2];
            #pragma unroll
            for (int mt = 0; mt < 2; mt++) {
                int m0 = wm + mt*16 + grp;
                ah[mt][0] = sm[k2r *SA + m0];
                ah[mt][1] = sm[k2r *SA + m0 + 8];
                ah[mt][2] = sm[k2r4*SA + m0];
                ah[mt][3] = sm[k2r4*SA + m0 + 8];
                al[mt][0] = sm[AOFF_L + k2r *SA + m0];
                al[mt][1] = sm[AOFF_L + k2r *SA + m0 + 8];
                al[mt][2] = sm[AOFF_L + k2r4*SA + m0];
                al[mt][3] = sm[AOFF_L + k2r4*SA + m0 + 8];
            }
            #pragma unroll
            for (int nt = 0; nt < 4; nt++) {
                int n0 = wn + nt*8 + grp;
                bh[nt][0] = sm[BOFF_H + k2r *SBN + n0];
                bh[nt][1] = sm[BOFF_H + k2r4*SBN + n0];
                bl[nt][0] = sm[BOFF_L + k2r *SBN + n0];
                bl[nt][1] = sm[BOFF_L + k2r4*SBN + n0];
            }
            #pragma unroll
            for (int mt = 0; mt < 2; mt++)
                #pragma unroll
                for (int nt = 0; nt < 4; nt++) {
                    mma16n8k16bf(acc[mt][nt], ah[mt], bh[nt]);
                    mma16n8k16bf(acc[mt][nt], ah[mt], bl[nt]);
                    mma16n8k16bf(acc[mt][nt], al[mt], bh[nt]);
                }
        }
        __syncthreads();
    }

    // ---- epilogue: bias + activation + store ----
    int nHalf = (blockIdx.x & 1)*64;
    #pragma unroll
    for (int mt = 0; mt < 2; mt++) {
        #pragma unroll
        for (int half = 0; half < 2; half++) {
            int rm = rowBase + wm + mt*16 + grp + half*8;
            if (rm >= NROWS) continue;
            float plb = 0.f, Esc = 0.f;
            if      (g == 0) plb = g_Plb[rm];
            else if (g == 1) Esc = x[(size_t)rm*6 + 1];
            #pragma unroll
            for (int nt = 0; nt < 4; nt++) {
                int colg = nHalf + wn + nt*8 + 2*tig;
                float v0 = acc[mt][nt][half*2 + 0] + __ldg(&b2[g*128 + colg]);
                float v1 = acc[mt][nt][half*2 + 1] + __ldg(&b2[g*128 + colg + 1]);
                float2 o;
                if (g == 0) {
                    o.x = plb * fminf(fmaxf(v0*(1.f/3.f) + 0.5f, 0.f), 1.f);
                    o.y = plb * fminf(fmaxf(v1*(1.f/3.f) + 0.5f, 0.f), 1.f);
                    *(float2*)&g_Pl[(size_t)rm*NH + colg] = o;
                } else if (g == 1) {
                    o.x = Esc * fmaxf(v0, 0.f) * 2.f;
                    o.y = Esc * fmaxf(v1, 0.f) * 2.f;
                    *(float2*)&g_Ev[(size_t)rm*NH + colg] = o;
                } else {
                    o.x = __expf(v0);
                    o.y = __expf(v1);
                    *(float2*)&g_vm[(size_t)rm*NH + colg] = o;
                }
            }
        }
    }
}

// ====== Kernel 3: fused scan + conv, barrier-free, fast-exp =======================
#define PD 8
__global__ void __launch_bounds__(128) scanwarp_kernel(
    const float* __restrict__ x, const float* __restrict__ fcCT_w)
{
    int s = blockIdx.x, h = threadIdx.x;
    int lane = h & 31, warp = h >> 5;
    const float* G = g_gates + s*6*NH;
    float kp = G[0*NH+h], ksv = G[1*NH+h], kg = G[2*NH+h];
    float gp = G[3*NH+h], gL  = G[4*NH+h], qb = G[5*NH+h];
    float cc0 = g_cc[s*NDIM + h];
    float cc1 = g_cc[s*NDIM + NH + h];
    float cc2 = g_cc[s*NDIM + 2*NH + h];
    float wp1 = fcCT_w[(h)*34 + 0],      wp2 = fcCT_w[(h)*34 + 1];
    float ws1 = fcCT_w[(NH+h)*34 + 0],   ws2 = fcCT_w[(NH+h)*34 + 1];
    float wg1 = fcCT_w[(2*NH+h)*34 + 0], wg2 = fcCT_w[(2*NH+h)*34 + 1];

    float rg[NR];
    #pragma unroll
    for (int i = 0; i < NR; i++) rg[i] = g_rg[s*NH*NR + h*NR + i];

    float qh[NR], ch[NR];
    #pragma unroll
    for (int i = 0; i < NR; i++) { qh[i] = 0.f; ch[i] = 0.f; }

    float Sf = 0.f, Ss = 0.f, Sg = 0.f;
    const int base = s*NH + h;
    float pl[PD], ev[PD], vm[PD];
    #pragma unroll
    for (int j = 0; j < PD; j++) {
        int ix = j*NS*NH + base;
        pl[j] = g_Pl[ix]; ev[j] = g_Ev[ix]; vm[j] = g_vm[ix];
    }

    for (int t0 = 0; t0 < NT; t0 += PD) {
        #pragma unroll
        for (int j = 0; j < PD; j++) {
            int t = t0 + j;
            if (t >= NT) break;                 // uniform across block
            int rm = t*NS + s;
            float Psv = g_Ps[rm];
            float T1  = x[(size_t)rm*6 + 2];
            float T2  = x[(size_t)rm*6 + 3];

            float a  = Sf + Psv;
            float qf = fminf(a, vm[j]);
            Sf = fmaxf(a - vm[j], 0.f);
            float H  = fmaxf(Ss + pl[j] + qf - ev[j], 0.f);
            float qp = fmaxf(kp*(H - gL), 0.f);
            float qs = ksv * fminf(H, gL);
            Ss = H - qp - qs;
            float qso = qs*(1.f - gp);
            float qsg = qs*gp;
            float sg2 = Sg + qsg;
            float qg  = kg*sg2 + qb;
            Sg = (1.f - kg)*sg2 - qb;

            float cp = __expf(cc0 + T1*wp1 + T2*wp2);
            float cs = __expf(cc1 + T1*ws1 + T2*ws2);
            float cg = __expf(cc2 + T1*wg1 + T2*wg2);

            float QS = qp + qso + qg;
            float CS = qp*cp*0.1f + qso*cs + qg*cg;

            int tn = t + PD;
            if (tn < NT) {
                int ix = tn*NS*NH + base;
                pl[j] = g_Pl[ix]; ev[j] = g_Ev[ix]; vm[j] = g_vm[ix];
            }

            #pragma unroll
            for (int i = NR-1; i >= 1; i--) { qh[i] = qh[i-1]; ch[i] = ch[i-1]; }
            qh[0] = QS; ch[0] = CS;
            float pq = 0.f, pc = 0.f;
            #pragma unroll
            for (int i = 0; i < NR; i++) { pq += qh[i]*rg[i]; pc += ch[i]*rg[i]; }

            #pragma unroll
            for (int o = 16; o; o >>= 1) {
                pq += __shfl_down_sync(0xffffffffu, pq, o);
                pc += __shfl_down_sync(0xffffffffu, pc, o);
            }
            if (lane == 0) {
                int pix = rm*4 + warp;
                g_pq[pix] = pq;
                g_pc[pix] = pc;
            }
        }
    }
}

// ============ Kernel 4: combine per-warp partials -> outQ, outC ===================
__global__ void __launch_bounds__(256) combine_kernel(float* __restrict__ out)
{
    int idx = blockIdx.x*256 + threadIdx.x;    // idx = t*NS + s
    if (idx >= NROWS) return;
    const float4 q4 = *(const float4*)&g_pq[idx*4];
    const float4 c4 = *(const float4*)&g_pc[idx*4];
    float q = ((q4.x + q4.y) + q4.z) + q4.w;
    float c = ((c4.x + c4.y) + c4.z) + c4.w;
    out[idx]         = q;
    out[NROWS + idx] = c / q;
}

// ==================================== launch ======================================
extern "C" void kernel_launch(void* const* d_in, const int* in_sizes, int n_in,
                              void* d_out, int out_size)
{
    const float* x       = (const float*)d_in[0];
    const float* xc      = (const float*)d_in[1];
    const float* fcR_w1  = (const float*)d_in[2];
    const float* fcR_b1  = (const float*)d_in[3];
    const float* fcR_w2  = (const float*)d_in[4];
    const float* fcR_b2  = (const float*)d_in[5];
    const float* fcW_w1  = (const float*)d_in[6];
    const float* fcW_b1  = (const float*)d_in[7];
    const float* fcW_w2  = (const float*)d_in[8];
    const float* fcW_b2  = (const float*)d_in[9];
    const float* fcT_w1  = (const float*)d_in[10];
    const float* fcT_b1  = (const float*)d_in[11];
    const float* fcT_w2  = (const float*)d_in[12];
    const float* fcT_b2  = (const float*)d_in[13];
    const float* fcCT_w  = (const float*)d_in[14];
    const float* fcCT_b  = (const float*)d_in[15];
    float* out = (float*)d_out;

    site_kernel<<<NS/SB, 256>>>(xc, fcR_w1, fcR_b1, fcR_w2, fcR_b2,
                                fcW_w1, fcW_b1, fcW_w2, fcW_b2,
                                fcT_w1, fcT_b1, fcCT_w, fcCT_b);        // launch 1
    split_w_kernel<<<(NDIM*K2DIM + 255)/256, 256>>>(fcT_w2);             // launch 2
    hidden_kernel<<<NROWS, 128>>>(x, fcT_w1);                            // launch 3
    dim3 gg(6, NTILES);
    fct_mma_kernel<<<gg, 256, SM_BYTES>>>(x, fcT_b2);                    // launch 4 <- ncu capture
    scanwarp_kernel<<<NS, 128>>>(x, fcCT_w);                             // launch 5
    combine_kernel<<<(NROWS + 255)/256, 256>>>(out);                     // launch 6
}

// round 15
// speedup vs baseline: 1.0429x; 1.0429x over previous
#include <cuda_runtime.h>
#include <math.h>
#include <stdint.h>

// Problem constants
#define NT 365
#define NS 300
#define NH 128
#define NG 32
#define NR 8
#define NROWS (NT*NS)          // 109500
#define KDIM 256
#define K2DIM 128              // bf16x2 words per row
#define NDIM 384               // NH*3
#define MTILE 128
#define NTILES ((NROWS + MTILE - 1)/MTILE)   // 856

// ---------------- scratch (device globals; no allocation in kernel_launch) --------
__device__ uint32_t g_Hh[NROWS*K2DIM];   // H hi bf16x2, [row][k2]
__device__ uint32_t g_Hl[NROWS*K2DIM];   // H lo bf16x2
__device__ uint32_t g_Wh[NDIM*K2DIM];    // W2 hi bf16x2, [n][k2]
__device__ uint32_t g_Wl[NDIM*K2DIM];    // W2 lo bf16x2
__device__ float g_Pl[NROWS*NH];         // rain per bucket
__device__ float g_Ev[NROWS*NH];         // evap per bucket
__device__ float g_vm[NROWS*NH];         // melt cap
__device__ float g_Ps [NROWS];           // snow precip (scalar per row)
__device__ float g_Plb[NROWS];           // P*(1-vf)
__device__ float g_cT[NS*KDIM];          // fcT layer1 static part [s][k] (incl b1)
__device__ float g_cc[NS*NDIM];          // fcCT static part (incl bias)
__device__ float g_gates[NS*6*NH];       // kp,ks,kg,gp,gL,qb
__device__ float g_rg[NS*NH*NR];         // relu(r) * ga  (ga folded into taps)
__device__ float g_pq[NROWS*4];          // per-warp partial sums of Q-conv
__device__ float g_pc[NROWS*4];          // per-warp partial sums of C-conv

// =============================== small helpers ====================================
__device__ __forceinline__ uint32_t pack_bf16(float lo, float hi) {
    uint32_t r; asm("cvt.rn.bf16x2.f32 %0, %1, %2;" : "=r"(r) : "f"(hi), "f"(lo));
    return r;
}
__device__ __forceinline__ void mma16n8k16bf(float* c, const uint32_t* a, const uint32_t* b) {
    asm volatile("mma.sync.aligned.m16n8k16.row.col.f32.bf16.bf16.f32 "
        "{%0,%1,%2,%3}, {%4,%5,%6,%7}, {%8,%9}, {%0,%1,%2,%3};"
        : "+f"(c[0]), "+f"(c[1]), "+f"(c[2]), "+f"(c[3])
        : "r"(a[0]), "r"(a[1]), "r"(a[2]), "r"(a[3]), "r"(b[0]), "r"(b[1]));
}
__device__ __forceinline__ void split2(float a, float b, uint32_t& ph, uint32_t& pl) {
    ph = pack_bf16(a, b);
    float r0 = a - __uint_as_float(ph << 16);
    float r1 = b - __uint_as_float(ph & 0xFFFF0000u);
    pl = pack_bf16(r0, r1);
}

// ======================= Kernel 1: per-site MLPs (fcW, fcR, statics) ==============
#define SB 6    // sites per block; 300/6 = 50 blocks
__global__ void __launch_bounds__(256) site_kernel(
    const float* __restrict__ xc,
    const float* __restrict__ fcR_w1, const float* __restrict__ fcR_b1,
    const float* __restrict__ fcR_w2, const float* __restrict__ fcR_b2,
    const float* __restrict__ fcW_w1, const float* __restrict__ fcW_b1,
    const float* __restrict__ fcW_w2, const float* __restrict__ fcW_b2,
    const float* __restrict__ fcT_w1, const float* __restrict__ fcT_b1,
    const float* __restrict__ fcCT_w, const float* __restrict__ fcCT_b)
{
    int s0  = blockIdx.x * SB;
    int tid = threadIdx.x;
    int lane = tid & 31, warp = tid >> 5;
    __shared__ float sxc[SB][32];
    __shared__ float hW [SB][257];
    __shared__ float hR [SB][257];
    __shared__ float sga[SB][128];

    for (int i = tid; i < SB*32; i += 256)
        sxc[i/32][i%32] = xc[(s0 + i/32)*32 + (i%32)];
    __syncthreads();

    {
        int k = tid;
        float aW[SB], aR[SB], aT[SB];
        #pragma unroll
        for (int s = 0; s < SB; s++) { aW[s]=0.f; aR[s]=0.f; aT[s]=0.f; }
        for (int j = 0; j < 32; j++) {
            float wW = fcW_w1[k*32 + j];
            float wR = fcR_w1[k*32 + j];
            float wT = fcT_w1[k*38 + 6 + j];
            #pragma unroll
            for (int s = 0; s < SB; s++) {
                float xv = sxc[s][j];
                aW[s] += wW*xv; aR[s] += wR*xv; aT[s] += wT*xv;
            }
        }
        float bW = fcW_b1[k], bR = fcR_b1[k], bT = fcT_b1[k];
        #pragma unroll
        for (int s = 0; s < SB; s++) {
            hW[s][k] = tanhf(aW[s] + bW);
            hR[s][k] = tanhf(aR[s] + bR);
            g_cT[(s0+s)*KDIM + k] = aT[s] + bT;
        }
    }
    for (int o = tid; o < NDIM; o += 256) {
        float acc[SB];
        float b = fcCT_b[o];
        #pragma unroll
        for (int s = 0; s < SB; s++) acc[s] = b;
        for (int j = 0; j < 32; j++) {
            float w = fcCT_w[o*34 + 2 + j];
            #pragma unroll
            for (int s = 0; s < SB; s++) acc[s] += w * sxc[s][j];
        }
        #pragma unroll
        for (int s = 0; s < SB; s++) g_cc[(s0+s)*NDIM + o] = acc[s];
    }
    __syncthreads();

    // fcW layer 2 -> gates: warp-per-output; lane covers k = j*32+lane, j=0..7
    for (int i = 0; i < 7*NH/8; i++) {
        int o = i*8 + warp;
        float w[8];
        #pragma unroll
        for (int j = 0; j < 8; j++) w[j] = fcW_w2[o*KDIM + j*32 + lane];
        float acc[SB];
        #pragma unroll
        for (int s = 0; s < SB; s++) {
            float a = 0.f;
            #pragma unroll
            for (int j = 0; j < 8; j++) a += w[j]*hW[s][j*32 + lane];
            acc[s] = a;
        }
        #pragma unroll
        for (int off = 16; off; off >>= 1)
            #pragma unroll
            for (int s = 0; s < SB; s++)
                acc[s] += __shfl_down_sync(0xffffffffu, acc[s], off);
        if (lane == 0) {
            float b = fcW_b2[o];
            int g = o >> 7, h = o & 127;
            #pragma unroll
            for (int s = 0; s < SB; s++) {
                float a = acc[s] + b;
                if      (g < 4)  g_gates[(s0+s)*6*NH + g*NH + h] = 1.f/(1.f + expf(-a));
                else if (g == 4) g_gates[(s0+s)*6*NH + 4*NH + h] = expf(a)*2.f;
                else if (g == 5) g_gates[(s0+s)*6*NH + 5*NH + h] = fmaxf(a, 0.f);
                else             sga[s][h] = a;
            }
        }
    }
    __syncthreads();

    if (tid < SB) {
        float m = -1e30f;
        for (int h = 0; h < NH; h++) m = fmaxf(m, sga[tid][h]);
        float sum = 0.f;
        for (int h = 0; h < NH; h++) { float e = expf(sga[tid][h] - m); sga[tid][h] = e; sum += e; }
        float inv = 1.f / sum;
        for (int h = 0; h < NH; h++) sga[tid][h] *= inv;
    }
    __syncthreads();

    for (int i = 0; i < NH*NR/8; i++) {
        int o = i*8 + warp;
        float w[8];
        #pragma unroll
        for (int j = 0; j < 8; j++) w[j] = fcR_w2[o*KDIM + j*32 + lane];
        float acc[SB];
        #pragma unroll
        for (int s = 0; s < SB; s++) {
            float a = 0.f;
            #pragma unroll
            for (int j = 0; j < 8; j++) a += w[j]*hR[s][j*32 + lane];
            acc[s] = a;
        }
        #pragma unroll
        for (int off = 16; off; off >>= 1)
            #pragma unroll
            for (int s = 0; s < SB; s++)
                acc[s] += __shfl_down_sync(0xffffffffu, acc[s], off);
        if (lane == 0) {
            float b = fcR_b2[o];
            int h = o >> 3;
            #pragma unroll
            for (int s = 0; s < SB; s++)
                g_rg[(s0+s)*NH*NR + o] = fmaxf(acc[s] + b, 0.f) * sga[s][h];
        }
    }
}

// ============== Kernel 1b: pre-split W2 into bf16 hi/lo (runs once) ===============
__global__ void __launch_bounds__(256) split_w_kernel(const float* __restrict__ W2)
{
    int idx = blockIdx.x*256 + threadIdx.x;    // n*K2DIM + k2
    if (idx >= NDIM*K2DIM) return;
    int n = idx >> 7, k2 = idx & 127;
    float2 v = *(const float2*)&W2[(size_t)n*KDIM + 2*k2];
    uint32_t ph, pl;
    split2(v.x, v.y, ph, pl);
    g_Wh[idx] = ph;
    g_Wl[idx] = pl;
}

// ====== Kernel 2a: fcT layer-1 tanh ONCE -> bf16 hi/lo pairs + snow split =========
__global__ void __launch_bounds__(128) hidden_kernel(
    const float* __restrict__ x, const float* __restrict__ fcT_w1)
{
    int rm = blockIdx.x;             // row = t*NS + s
    int k2 = threadIdx.x;            // 0..127
    int s  = rm % NS;
    const float* xr = x + (size_t)rm*6;
    int k0 = 2*k2;
    float acc0 = g_cT[s*KDIM + k0];
    float acc1 = g_cT[s*KDIM + k0 + 1];
    #pragma unroll
    for (int j = 0; j < 6; j++) {
        float xv = xr[j];
        acc0 += fcT_w1[k0*38 + j]     * xv;
        acc1 += fcT_w1[(k0+1)*38 + j] * xv;
    }
    float h0 = tanhf(acc0), h1 = tanhf(acc1);
    uint32_t ph, pl;
    split2(h0, h1, ph, pl);
    size_t o = (size_t)rm*K2DIM + k2;
    g_Hh[o] = ph;
    g_Hl[o] = pl;

    if (k2 == 0) {
        float P = xr[0], T1 = xr[2], T2 = xr[3];
        float d = T2 - T1;
        float ratio = (T1 + T2) / (d == 0.f ? 1.f : d);
        ratio = fminf(fmaxf(ratio, -1.f), 1.f);
        float vf = acosf(ratio) / 3.1415f;
        if (T1 >= 0.f) vf = 0.f;
        else if (T2 <= 0.f) vf = 1.f;
        g_Ps [rm] = P * vf;
        g_Plb[rm] = P * (1.f - vf);
    }
}

// ===== Kernel 2b: fcT layer-2, 3x-BF16 mma GEMM, CTA tile 128x128 =================
// grid = (3 activation groups, 856 row tiles). Warp tile 32(m) x 64(n).
// SMEM (uint32 bf16x2, k2-major, stride SA): Ah[16][136], Al, Bh[16][136], Bl
#define SA 136
#define AOFF_L (16*SA)
#define BOFF_H (2*16*SA)
#define BOFF_L (3*16*SA)
#define SM_WORDS (4*16*SA)
#define SM_BYTES (SM_WORDS*4)            // 34816

__global__ void __launch_bounds__(256)
fct_mma_kernel(const float* __restrict__ x, const float* __restrict__ b2)
{
    extern __shared__ uint32_t sm[];
    int tid  = threadIdx.x;
    int lane = tid & 31, wid = tid >> 5;
    int wm = (wid & 3) * 32;            // warp m-offset within 128
    int wn = (wid >> 2) * 64;           // warp n-offset within 128
    int grp = lane >> 2, tig = lane & 3;
    int rowBase = blockIdx.y * MTILE;
    int g       = blockIdx.x;           // activation group 0..2
    int nBase   = g * 128;

    float acc[2][8][4];
    #pragma unroll
    for (int mt = 0; mt < 2; mt++)
        #pragma unroll
        for (int nt = 0; nt < 8; nt++)
            #pragma unroll
            for (int q = 0; q < 4; q++) acc[mt][nt][q] = 0.f;

    int ar   = tid >> 1;          // A-fill row 0..127
    int ahal = tid & 1;           // which 8-word half of the 16 k2 slice
    int rmA  = rowBase + ar;
    bool aok = rmA < NROWS;

    for (int chunk = 0; chunk < 8; chunk++) {
        int kb = chunk * 16;       // k2 base
        // ---- fill A: copy of pre-split pairs ----
        {
            size_t src = (size_t)rmA*K2DIM + kb + ahal*8;
            uint4 h0 = make_uint4(0,0,0,0), h1 = h0, l0 = h0, l1 = h0;
            if (aok) {
                h0 = *(const uint4*)&g_Hh[src];
                h1 = *(const uint4*)&g_Hh[src + 4];
                l0 = *(const uint4*)&g_Hl[src];
                l1 = *(const uint4*)&g_Hl[src + 4];
            }
            int kl = ahal*8;
            const uint32_t* hp = (const uint32_t*)&h0;
            const uint32_t* lp = (const uint32_t*)&l0;
            #pragma unroll
            for (int w = 0; w < 4; w++) {
                sm[(kl+w)*SA + ar]          = hp[w];
                sm[AOFF_L + (kl+w)*SA + ar] = lp[w];
            }
            hp = (const uint32_t*)&h1; lp = (const uint32_t*)&l1;
            #pragma unroll
            for (int w = 0; w < 4; w++) {
                sm[(kl+4+w)*SA + ar]          = hp[w];
                sm[AOFF_L + (kl+4+w)*SA + ar] = lp[w];
            }
        }
        // ---- fill B: 128 n x 16 k2, copy of pre-split pairs ----
        #pragma unroll
        for (int i = 0; i < 8; i++) {
            int idx = tid + i*256;            // 2048 = 128 n x 16 k2
            int n = idx >> 4, k2l = idx & 15;
            size_t src = (size_t)(nBase + n)*K2DIM + kb + k2l;
            sm[BOFF_H + k2l*SA + n] = g_Wh[src];
            sm[BOFF_L + k2l*SA + n] = g_Wl[src];
        }
        __syncthreads();

        // ---- 2 k16-steps of mma ----
        #pragma unroll
        for (int ks = 0; ks < 2; ks++) {
            int k2r  = ks*8 + tig;
            int k2r4 = k2r + 4;
            uint32_t ah[2][4], al[2][4], bh[8][2], bl[8][2];
            #pragma unroll
            for (int mt = 0; mt < 2; mt++) {
                int m0 = wm + mt*16 + grp;
                ah[mt][0] = sm[k2r *SA + m0];
                ah[mt][1] = sm[k2r *SA + m0 + 8];
                ah[mt][2] = sm[k2r4*SA + m0];
                ah[mt][3] = sm[k2r4*SA + m0 + 8];
                al[mt][0] = sm[AOFF_L + k2r *SA + m0];
                al[mt][1] = sm[AOFF_L + k2r *SA + m0 + 8];
                al[mt][2] = sm[AOFF_L + k2r4*SA + m0];
                al[mt][3] = sm[AOFF_L + k2r4*SA + m0 + 8];
            }
            #pragma unroll
            for (int nt = 0; nt < 8; nt++) {
                int n0 = wn + nt*8 + grp;
                bh[nt][0] = sm[BOFF_H + k2r *SA + n0];
                bh[nt][1] = sm[BOFF_H + k2r4*SA + n0];
                bl[nt][0] = sm[BOFF_L + k2r *SA + n0];
                bl[nt][1] = sm[BOFF_L + k2r4*SA + n0];
            }
            #pragma unroll
            for (int mt = 0; mt < 2; mt++)
                #pragma unroll
                for (int nt = 0; nt < 8; nt++) {
                    mma16n8k16bf(acc[mt][nt], ah[mt], bh[nt]);
                    mma16n8k16bf(acc[mt][nt], ah[mt], bl[nt]);
                    mma16n8k16bf(acc[mt][nt], al[mt], bh[nt]);
                }
        }
        __syncthreads();
    }

    // ---- epilogue: bias + activation + store (g uniform per CTA) ----
    #pragma unroll
    for (int mt = 0; mt < 2; mt++) {
        #pragma unroll
        for (int half = 0; half < 2; half++) {
            int rm = rowBase + wm + mt*16 + grp + half*8;
            if (rm >= NROWS) continue;
            float plb = 0.f, Esc = 0.f;
            if      (g == 0) plb = g_Plb[rm];
            else if (g == 1) Esc = x[(size_t)rm*6 + 1];
            #pragma unroll
            for (int nt = 0; nt < 8; nt++) {
                int colg = wn + nt*8 + 2*tig;      // column within NH group
                float v0 = acc[mt][nt][half*2 + 0] + __ldg(&b2[g*128 + colg]);
                float v1 = acc[mt][nt][half*2 + 1] + __ldg(&b2[g*128 + colg + 1]);
                float2 o;
                if (g == 0) {
                    o.x = plb * fminf(fmaxf(v0*(1.f/3.f) + 0.5f, 0.f), 1.f);
                    o.y = plb * fminf(fmaxf(v1*(1.f/3.f) + 0.5f, 0.f), 1.f);
                    *(float2*)&g_Pl[(size_t)rm*NH + colg] = o;
                } else if (g == 1) {
                    o.x = Esc * fmaxf(v0, 0.f) * 2.f;
                    o.y = Esc * fmaxf(v1, 0.f) * 2.f;
                    *(float2*)&g_Ev[(size_t)rm*NH + colg] = o;
                } else {
                    o.x = __expf(v0);
                    o.y = __expf(v1);
                    *(float2*)&g_vm[(size_t)rm*NH + colg] = o;
                }
            }
        }
    }
}

// ====== Kernel 3: fused scan + conv, barrier-free =================================
#define PD 8
__global__ void __launch_bounds__(128) scanwarp_kernel(
    const float* __restrict__ x, const float* __restrict__ fcCT_w)
{
    int s = blockIdx.x, h = threadIdx.x;
    int lane = h & 31, warp = h >> 5;
    const float* G = g_gates + s*6*NH;
    float kp = G[0*NH+h], ksv = G[1*NH+h], kg = G[2*NH+h];
    float gp = G[3*NH+h], gL  = G[4*NH+h], qb = G[5*NH+h];
    float cc0 = g_cc[s*NDIM + h];
    float cc1 = g_cc[s*NDIM + NH + h];
    float cc2 = g_cc[s*NDIM + 2*NH + h];
    float wp1 = fcCT_w[(h)*34 + 0],      wp2 = fcCT_w[(h)*34 + 1];
    float ws1 = fcCT_w[(NH+h)*34 + 0],   ws2 = fcCT_w[(NH+h)*34 + 1];
    float wg1 = fcCT_w[(2*NH+h)*34 + 0], wg2 = fcCT_w[(2*NH+h)*34 + 1];

    float rg[NR];
    #pragma unroll
    for (int i = 0; i < NR; i++) rg[i] = g_rg[s*NH*NR + h*NR + i];

    float qh[NR], ch[NR];
    #pragma unroll
    for (int i = 0; i < NR; i++) { qh[i] = 0.f; ch[i] = 0.f; }

    float Sf = 0.f, Ss = 0.f, Sg = 0.f;
    const int base = s*NH + h;
    float pl[PD], ev[PD], vm[PD];
    #pragma unroll
    for (int j = 0; j < PD; j++) {
        int ix = j*NS*NH + base;
        pl[j] = g_Pl[ix]; ev[j] = g_Ev[ix]; vm[j] = g_vm[ix];
    }

    for (int t0 = 0; t0 < NT; t0 += PD) {
        #pragma unroll
        for (int j = 0; j < PD; j++) {
            int t = t0 + j;
            if (t >= NT) break;                 // uniform across block
            int rm = t*NS + s;
            float Psv = g_Ps[rm];
            float T1  = x[(size_t)rm*6 + 2];
            float T2  = x[(size_t)rm*6 + 3];

            float a  = Sf + Psv;
            float qf = fminf(a, vm[j]);
            Sf = fmaxf(a - vm[j], 0.f);
            float H  = fmaxf(Ss + pl[j] + qf - ev[j], 0.f);
            float qp = fmaxf(kp*(H - gL), 0.f);
            float qs = ksv * fminf(H, gL);
            Ss = H - qp - qs;
            float qso = qs*(1.f - gp);
            float qsg = qs*gp;
            float sg2 = Sg + qsg;
            float qg  = kg*sg2 + qb;
            Sg = (1.f - kg)*sg2 - qb;

            float cp = __expf(cc0 + T1*wp1 + T2*wp2);
            float cs = __expf(cc1 + T1*ws1 + T2*ws2);
            float cg = __expf(cc2 + T1*wg1 + T2*wg2);

            float QS = qp + qso + qg;
            float CS = qp*cp*0.1f + qso*cs + qg*cg;

            int tn = t + PD;
            if (tn < NT) {
                int ix = tn*NS*NH + base;
                pl[j] = g_Pl[ix]; ev[j] = g_Ev[ix]; vm[j] = g_vm[ix];
            }

            #pragma unroll
            for (int i = NR-1; i >= 1; i--) { qh[i] = qh[i-1]; ch[i] = ch[i-1]; }
            qh[0] = QS; ch[0] = CS;
            float pq = 0.f, pc = 0.f;
            #pragma unroll
            for (int i = 0; i < NR; i++) { pq += qh[i]*rg[i]; pc += ch[i]*rg[i]; }

            #pragma unroll
            for (int o = 16; o; o >>= 1) {
                pq += __shfl_down_sync(0xffffffffu, pq, o);
                pc += __shfl_down_sync(0xffffffffu, pc, o);
            }
            if (lane == 0) {
                int pix = rm*4 + warp;
                g_pq[pix] = pq;
                g_pc[pix] = pc;
            }
        }
    }
}

// ============ Kernel 4: combine per-warp partials -> outQ, outC ===================
__global__ void __launch_bounds__(256) combine_kernel(float* __restrict__ out)
{
    int idx = blockIdx.x*256 + threadIdx.x;    // idx = t*NS + s
    if (idx >= NROWS) return;
    const float4 q4 = *(const float4*)&g_pq[idx*4];
    const float4 c4 = *(const float4*)&g_pc[idx*4];
    float q = ((q4.x + q4.y) + q4.z) + q4.w;
    float c = ((c4.x + c4.y) + c4.z) + c4.w;
    out[idx]         = q;
    out[NROWS + idx] = c / q;
}

// ==================================== launch ======================================
extern "C" void kernel_launch(void* const* d_in, const int* in_sizes, int n_in,
                              void* d_out, int out_size)
{
    const float* x       = (const float*)d_in[0];
    const float* xc      = (const float*)d_in[1];
    const float* fcR_w1  = (const float*)d_in[2];
    const float* fcR_b1  = (const float*)d_in[3];
    const float* fcR_w2  = (const float*)d_in[4];
    const float* fcR_b2  = (const float*)d_in[5];
    const float* fcW_w1  = (const float*)d_in[6];
    const float* fcW_b1  = (const float*)d_in[7];
    const float* fcW_w2  = (const float*)d_in[8];
    const float* fcW_b2  = (const float*)d_in[9];
    const float* fcT_w1  = (const float*)d_in[10];
    const float* fcT_b1  = (const float*)d_in[11];
    const float* fcT_w2  = (const float*)d_in[12];
    const float* fcT_b2  = (const float*)d_in[13];
    const float* fcCT_w  = (const float*)d_in[14];
    const float* fcCT_b  = (const float*)d_in[15];
    float* out = (float*)d_out;

    site_kernel<<<NS/SB, 256>>>(xc, fcR_w1, fcR_b1, fcR_w2, fcR_b2,
                                fcW_w1, fcW_b1, fcW_w2, fcW_b2,
                                fcT_w1, fcT_b1, fcCT_w, fcCT_b);        // launch 1
    split_w_kernel<<<(NDIM*K2DIM + 255)/256, 256>>>(fcT_w2);             // launch 2
    hidden_kernel<<<NROWS, 128>>>(x, fcT_w1);                            // launch 3
    dim3 gg(3, NTILES);
    fct_mma_kernel<<<gg, 256, SM_BYTES>>>(x, fcT_b2);                    // launch 4 <- ncu capture
    scanwarp_kernel<<<NS, 128>>>(x, fcCT_w);                             // launch 5
    combine_kernel<<<(NROWS + 255)/256, 256>>>(out);                     // launch 6
}

// round 16
// speedup vs baseline: 1.0552x; 1.0118x over previous
#include <cuda_runtime.h>
#include <math.h>
#include <stdint.h>

// Problem constants
#define NT 365
#define NS 300
#define NH 128
#define NG 32
#define NR 8
#define NROWS (NT*NS)          // 109500
#define KDIM 256
#define K2DIM 128              // bf16x2 words per row
#define NDIM 384               // NH*3
#define MTILE 128
#define NTILES ((NROWS + MTILE - 1)/MTILE)   // 856

// ---------------- scratch (device globals; no allocation in kernel_launch) --------
__device__ uint32_t g_Hh[NROWS*K2DIM];   // H hi bf16x2, [row][k2]
__device__ uint32_t g_Hl[NROWS*K2DIM];   // H lo bf16x2
__device__ uint32_t g_Wh[NDIM*K2DIM];    // W2 hi bf16x2, [n][k2]
__device__ uint32_t g_Wl[NDIM*K2DIM];    // W2 lo bf16x2
__device__ float g_Pl[NROWS*NH];         // rain per bucket
__device__ float g_Ev[NROWS*NH];         // evap per bucket
__device__ float g_vm[NROWS*NH];         // melt cap
__device__ float g_Ps [NROWS];           // snow precip (scalar per row)
__device__ float g_Plb[NROWS];           // P*(1-vf)
__device__ float g_cT[NS*KDIM];          // fcT layer1 static part [s][k] (incl b1)
__device__ float g_cc[NS*NDIM];          // fcCT static part (incl bias)
__device__ float g_gates[NS*6*NH];       // kp,ks,kg,gp,gL,qb
__device__ float g_rg[NS*NH*NR];         // relu(r) * ga  (ga folded into taps)
__device__ float g_pq[NROWS*4];          // per-warp partial sums of Q-conv
__device__ float g_pc[NROWS*4];          // per-warp partial sums of C-conv

// =============================== small helpers ====================================
__device__ __forceinline__ uint32_t pack_bf16(float lo, float hi) {
    uint32_t r; asm("cvt.rn.bf16x2.f32 %0, %1, %2;" : "=r"(r) : "f"(hi), "f"(lo));
    return r;
}
__device__ __forceinline__ void mma16n8k16bf(float* c, const uint32_t* a, const uint32_t* b) {
    asm volatile("mma.sync.aligned.m16n8k16.row.col.f32.bf16.bf16.f32 "
        "{%0,%1,%2,%3}, {%4,%5,%6,%7}, {%8,%9}, {%0,%1,%2,%3};"
        : "+f"(c[0]), "+f"(c[1]), "+f"(c[2]), "+f"(c[3])
        : "r"(a[0]), "r"(a[1]), "r"(a[2]), "r"(a[3]), "r"(b[0]), "r"(b[1]));
}
__device__ __forceinline__ void ldsm_x4(uint32_t* r, uint32_t addr) {
    asm volatile("ldmatrix.sync.aligned.m8n8.x4.shared.b16 {%0,%1,%2,%3}, [%4];"
        : "=r"(r[0]), "=r"(r[1]), "=r"(r[2]), "=r"(r[3]) : "r"(addr));
}
__device__ __forceinline__ uint32_t smem_u32(const void* p) {
    uint32_t a;
    asm("{ .reg .u64 t; cvta.to.shared.u64 t, %1; cvt.u32.u64 %0, t; }" : "=r"(a) : "l"(p));
    return a;
}
__device__ __forceinline__ void split2(float a, float b, uint32_t& ph, uint32_t& pl) {
    ph = pack_bf16(a, b);
    float r0 = a - __uint_as_float(ph << 16);
    float r1 = b - __uint_as_float(ph & 0xFFFF0000u);
    pl = pack_bf16(r0, r1);
}

// ======================= Kernel 1: per-site MLPs (fcW, fcR, statics) ==============
#define SB 6    // sites per block; 300/6 = 50 blocks
__global__ void __launch_bounds__(256) site_kernel(
    const float* __restrict__ xc,
    const float* __restrict__ fcR_w1, const float* __restrict__ fcR_b1,
    const float* __restrict__ fcR_w2, const float* __restrict__ fcR_b2,
    const float* __restrict__ fcW_w1, const float* __restrict__ fcW_b1,
    const float* __restrict__ fcW_w2, const float* __restrict__ fcW_b2,
    const float* __restrict__ fcT_w1, const float* __restrict__ fcT_b1,
    const float* __restrict__ fcCT_w, const float* __restrict__ fcCT_b)
{
    int s0  = blockIdx.x * SB;
    int tid = threadIdx.x;
    int lane = tid & 31, warp = tid >> 5;
    __shared__ float sxc[SB][32];
    __shared__ float hW [SB][257];
    __shared__ float hR [SB][257];
    __shared__ float sga[SB][128];

    for (int i = tid; i < SB*32; i += 256)
        sxc[i/32][i%32] = xc[(s0 + i/32)*32 + (i%32)];
    __syncthreads();

    {
        int k = tid;
        float aW[SB], aR[SB], aT[SB];
        #pragma unroll
        for (int s = 0; s < SB; s++) { aW[s]=0.f; aR[s]=0.f; aT[s]=0.f; }
        for (int j = 0; j < 32; j++) {
            float wW = fcW_w1[k*32 + j];
            float wR = fcR_w1[k*32 + j];
            float wT = fcT_w1[k*38 + 6 + j];
            #pragma unroll
            for (int s = 0; s < SB; s++) {
                float xv = sxc[s][j];
                aW[s] += wW*xv; aR[s] += wR*xv; aT[s] += wT*xv;
            }
        }
        float bW = fcW_b1[k], bR = fcR_b1[k], bT = fcT_b1[k];
        #pragma unroll
        for (int s = 0; s < SB; s++) {
            hW[s][k] = tanhf(aW[s] + bW);
            hR[s][k] = tanhf(aR[s] + bR);
            g_cT[(s0+s)*KDIM + k] = aT[s] + bT;
        }
    }
    for (int o = tid; o < NDIM; o += 256) {
        float acc[SB];
        float b = fcCT_b[o];
        #pragma unroll
        for (int s = 0; s < SB; s++) acc[s] = b;
        for (int j = 0; j < 32; j++) {
            float w = fcCT_w[o*34 + 2 + j];
            #pragma unroll
            for (int s = 0; s < SB; s++) acc[s] += w * sxc[s][j];
        }
        #pragma unroll
        for (int s = 0; s < SB; s++) g_cc[(s0+s)*NDIM + o] = acc[s];
    }
    __syncthreads();

    for (int i = 0; i < 7*NH/8; i++) {
        int o = i*8 + warp;
        float w[8];
        #pragma unroll
        for (int j = 0; j < 8; j++) w[j] = fcW_w2[o*KDIM + j*32 + lane];
        float acc[SB];
        #pragma unroll
        for (int s = 0; s < SB; s++) {
            float a = 0.f;
            #pragma unroll
            for (int j = 0; j < 8; j++) a += w[j]*hW[s][j*32 + lane];
            acc[s] = a;
        }
        #pragma unroll
        for (int off = 16; off; off >>= 1)
            #pragma unroll
            for (int s = 0; s < SB; s++)
                acc[s] += __shfl_down_sync(0xffffffffu, acc[s], off);
        if (lane == 0) {
            float b = fcW_b2[o];
            int g = o >> 7, h = o & 127;
            #pragma unroll
            for (int s = 0; s < SB; s++) {
                float a = acc[s] + b;
                if      (g < 4)  g_gates[(s0+s)*6*NH + g*NH + h] = 1.f/(1.f + expf(-a));
                else if (g == 4) g_gates[(s0+s)*6*NH + 4*NH + h] = expf(a)*2.f;
                else if (g == 5) g_gates[(s0+s)*6*NH + 5*NH + h] = fmaxf(a, 0.f);
                else             sga[s][h] = a;
            }
        }
    }
    __syncthreads();

    if (tid < SB) {
        float m = -1e30f;
        for (int h = 0; h < NH; h++) m = fmaxf(m, sga[tid][h]);
        float sum = 0.f;
        for (int h = 0; h < NH; h++) { float e = expf(sga[tid][h] - m); sga[tid][h] = e; sum += e; }
        float inv = 1.f / sum;
        for (int h = 0; h < NH; h++) sga[tid][h] *= inv;
    }
    __syncthreads();

    for (int i = 0; i < NH*NR/8; i++) {
        int o = i*8 + warp;
        float w[8];
        #pragma unroll
        for (int j = 0; j < 8; j++) w[j] = fcR_w2[o*KDIM + j*32 + lane];
        float acc[SB];
        #pragma unroll
        for (int s = 0; s < SB; s++) {
            float a = 0.f;
            #pragma unroll
            for (int j = 0; j < 8; j++) a += w[j]*hR[s][j*32 + lane];
            acc[s] = a;
        }
        #pragma unroll
        for (int off = 16; off; off >>= 1)
            #pragma unroll
            for (int s = 0; s < SB; s++)
                acc[s] += __shfl_down_sync(0xffffffffu, acc[s], off);
        if (lane == 0) {
            float b = fcR_b2[o];
            int h = o >> 3;
            #pragma unroll
            for (int s = 0; s < SB; s++)
                g_rg[(s0+s)*NH*NR + o] = fmaxf(acc[s] + b, 0.f) * sga[s][h];
        }
    }
}

// ============== Kernel 1b: pre-split W2 into bf16 hi/lo (runs once) ===============
__global__ void __launch_bounds__(256) split_w_kernel(const float* __restrict__ W2)
{
    int idx = blockIdx.x*256 + threadIdx.x;    // n*K2DIM + k2
    if (idx >= NDIM*K2DIM) return;
    int n = idx >> 7, k2 = idx & 127;
    float2 v = *(const float2*)&W2[(size_t)n*KDIM + 2*k2];
    uint32_t ph, pl;
    split2(v.x, v.y, ph, pl);
    g_Wh[idx] = ph;
    g_Wl[idx] = pl;
}

// ====== Kernel 2a: fcT layer-1 tanh ONCE -> bf16 hi/lo pairs + snow split =========
__global__ void __launch_bounds__(128) hidden_kernel(
    const float* __restrict__ x, const float* __restrict__ fcT_w1)
{
    int rm = blockIdx.x;             // row = t*NS + s
    int k2 = threadIdx.x;            // 0..127
    int s  = rm % NS;
    const float* xr = x + (size_t)rm*6;
    int k0 = 2*k2;
    float acc0 = g_cT[s*KDIM + k0];
    float acc1 = g_cT[s*KDIM + k0 + 1];
    #pragma unroll
    for (int j = 0; j < 6; j++) {
        float xv = xr[j];
        acc0 += fcT_w1[k0*38 + j]     * xv;
        acc1 += fcT_w1[(k0+1)*38 + j] * xv;
    }
    float h0 = tanhf(acc0), h1 = tanhf(acc1);
    uint32_t ph, pl;
    split2(h0, h1, ph, pl);
    size_t o = (size_t)rm*K2DIM + k2;
    g_Hh[o] = ph;
    g_Hl[o] = pl;

    if (k2 == 0) {
        float P = xr[0], T1 = xr[2], T2 = xr[3];
        float d = T2 - T1;
        float ratio = (T1 + T2) / (d == 0.f ? 1.f : d);
        ratio = fminf(fmaxf(ratio, -1.f), 1.f);
        float vf = acosf(ratio) / 3.1415f;
        if (T1 >= 0.f) vf = 0.f;
        else if (T2 <= 0.f) vf = 1.f;
        g_Ps [rm] = P * vf;
        g_Plb[rm] = P * (1.f - vf);
    }
}

// ===== Kernel 2b: fcT layer-2, 3x-BF16 mma GEMM, 128x128 tile, ldmatrix ===========
// SMEM layout (uint32 words): row-major [row][k2], stride RS=20 (banks {0,20,8,28,
// 16,4,24,12} per 8-row matrix => conflict-free ldmatrix).
// Regions: Ah[128][20], Al, Bh[128][20], Bl.
#define RS 20
#define A_L  (128*RS)
#define B_H  (2*128*RS)
#define B_L  (3*128*RS)
#define SM_WORDS (4*128*RS)
#define SM_BYTES (SM_WORDS*4)            // 40960

__global__ void __launch_bounds__(256)
fct_mma_kernel(const float* __restrict__ x, const float* __restrict__ b2)
{
    extern __shared__ uint32_t sm[];
    uint32_t smb = smem_u32(sm);
    int tid  = threadIdx.x;
    int lane = tid & 31, wid = tid >> 5;
    int wm = (wid & 3) * 32;            // warp m-offset within 128
    int wn = (wid >> 2) * 64;           // warp n-offset within 128
    int grp = lane >> 2, tig = lane & 3;
    int rowBase = blockIdx.y * MTILE;
    int g       = blockIdx.x;           // activation group 0..2
    int nBase   = g * 128;

    // per-lane ldmatrix row/col selectors
    int rsel = ((lane >> 3) & 1)*8 + (lane & 7);   // A: row within 16-row block
    int csel = (lane >> 4) * 4;                    // A: k2 col offset
    int rselB = ((lane >> 4) & 1)*8 + (lane & 7);  // B
    int cselB = ((lane >> 3) & 1)*4;

    float acc[2][8][4];
    #pragma unroll
    for (int mt = 0; mt < 2; mt++)
        #pragma unroll
        for (int nt = 0; nt < 8; nt++)
            #pragma unroll
            for (int q = 0; q < 4; q++) acc[mt][nt][q] = 0.f;

    int ar   = tid & 127;         // A-fill row
    int ahal = tid >> 7;          // which 8-word half of the 16 k2 slice
    int rmA  = rowBase + ar;
    bool aok = rmA < NROWS;

    for (int chunk = 0; chunk < 8; chunk++) {
        int kb = chunk * 16;       // k2 base
        // ---- fill A: row-major copy, 2x uint4 hi + 2x uint4 lo ----
        {
            size_t src = (size_t)rmA*K2DIM + kb + ahal*8;
            uint4 h0 = make_uint4(0,0,0,0), h1 = h0, l0 = h0, l1 = h0;
            if (aok) {
                h0 = *(const uint4*)&g_Hh[src];
                h1 = *(const uint4*)&g_Hh[src + 4];
                l0 = *(const uint4*)&g_Hl[src];
                l1 = *(const uint4*)&g_Hl[src + 4];
            }
            int dst = ar*RS + ahal*8;
            *(uint4*)&sm[dst]           = h0;
            *(uint4*)&sm[dst + 4]       = h1;
            *(uint4*)&sm[A_L + dst]     = l0;
            *(uint4*)&sm[A_L + dst + 4] = l1;
        }
        // ---- fill B: row-major copy, uint2 granules ----
        #pragma unroll
        for (int i = 0; i < 4; i++) {
            int idx = tid + i*256;            // 1024 = 128 n x 8 pairs
            int n = idx >> 3, kp = idx & 7;
            size_t src = (size_t)(nBase + n)*K2DIM + kb + 2*kp;
            int dst = n*RS + 2*kp;
            *(uint2*)&sm[B_H + dst] = *(const uint2*)&g_Wh[src];
            *(uint2*)&sm[B_L + dst] = *(const uint2*)&g_Wl[src];
        }
        __syncthreads();

        // ---- 2 k16-steps of mma, fragments via ldmatrix.x4 ----
        #pragma unroll
        for (int ks = 0; ks < 2; ks++) {
            uint32_t ah[2][4], al[2][4], bb[4][4], blb[4][4];
            #pragma unroll
            for (int mt = 0; mt < 2; mt++) {
                uint32_t a_off = 4u*((wm + mt*16 + rsel)*RS + ks*8 + csel);
                ldsm_x4(ah[mt], smb + a_off);
                ldsm_x4(al[mt], smb + A_L*4 + a_off);
            }
            #pragma unroll
            for (int p = 0; p < 4; p++) {
                uint32_t b_off = 4u*((wn + p*16 + rselB)*RS + ks*8 + cselB);
                ldsm_x4(bb[p],  smb + B_H*4 + b_off);
                ldsm_x4(blb[p], smb + B_L*4 + b_off);
            }
            #pragma unroll
            for (int mt = 0; mt < 2; mt++)
                #pragma unroll
                for (int p = 0; p < 4; p++) {
                    // nt = 2p:   regs 0,1 ; nt = 2p+1: regs 2,3
                    mma16n8k16bf(acc[mt][2*p  ], ah[mt], &bb[p][0]);
                    mma16n8k16bf(acc[mt][2*p  ], ah[mt], &blb[p][0]);
                    mma16n8k16bf(acc[mt][2*p  ], al[mt], &bb[p][0]);
                    mma16n8k16bf(acc[mt][2*p+1], ah[mt], &bb[p][2]);
                    mma16n8k16bf(acc[mt][2*p+1], ah[mt], &blb[p][2]);
                    mma16n8k16bf(acc[mt][2*p+1], al[mt], &bb[p][2]);
                }
        }
        __syncthreads();
    }

    // ---- epilogue: bias + activation + store (g uniform per CTA) ----
    #pragma unroll
    for (int mt = 0; mt < 2; mt++) {
        #pragma unroll
        for (int half = 0; half < 2; half++) {
            int rm = rowBase + wm + mt*16 + grp + half*8;
            if (rm >= NROWS) continue;
            float plb = 0.f, Esc = 0.f;
            if      (g == 0) plb = g_Plb[rm];
            else if (g == 1) Esc = x[(size_t)rm*6 + 1];
            #pragma unroll
            for (int nt = 0; nt < 8; nt++) {
                int colg = wn + nt*8 + 2*tig;
                float v0 = acc[mt][nt][half*2 + 0] + __ldg(&b2[g*128 + colg]);
                float v1 = acc[mt][nt][half*2 + 1] + __ldg(&b2[g*128 + colg + 1]);
                float2 o;
                if (g == 0) {
                    o.x = plb * fminf(fmaxf(v0*(1.f/3.f) + 0.5f, 0.f), 1.f);
                    o.y = plb * fminf(fmaxf(v1*(1.f/3.f) + 0.5f, 0.f), 1.f);
                    *(float2*)&g_Pl[(size_t)rm*NH + colg] = o;
                } else if (g == 1) {
                    o.x = Esc * fmaxf(v0, 0.f) * 2.f;
                    o.y = Esc * fmaxf(v1, 0.f) * 2.f;
                    *(float2*)&g_Ev[(size_t)rm*NH + colg] = o;
                } else {
                    o.x = __expf(v0);
                    o.y = __expf(v1);
                    *(float2*)&g_vm[(size_t)rm*NH + colg] = o;
                }
            }
        }
    }
}

// ====== Kernel 3: fused scan + conv, barrier-free =================================
#define PD 8
__global__ void __launch_bounds__(128) scanwarp_kernel(
    const float* __restrict__ x, const float* __restrict__ fcCT_w)
{
    int s = blockIdx.x, h = threadIdx.x;
    int lane = h & 31, warp = h >> 5;
    const float* G = g_gates + s*6*NH;
    float kp = G[0*NH+h], ksv = G[1*NH+h], kg = G[2*NH+h];
    float gp = G[3*NH+h], gL  = G[4*NH+h], qb = G[5*NH+h];
    float cc0 = g_cc[s*NDIM + h];
    float cc1 = g_cc[s*NDIM + NH + h];
    float cc2 = g_cc[s*NDIM + 2*NH + h];
    float wp1 = fcCT_w[(h)*34 + 0],      wp2 = fcCT_w[(h)*34 + 1];
    float ws1 = fcCT_w[(NH+h)*34 + 0],   ws2 = fcCT_w[(NH+h)*34 + 1];
    float wg1 = fcCT_w[(2*NH+h)*34 + 0], wg2 = fcCT_w[(2*NH+h)*34 + 1];

    float rg[NR];
    #pragma unroll
    for (int i = 0; i < NR; i++) rg[i] = g_rg[s*NH*NR + h*NR + i];

    float qh[NR], ch[NR];
    #pragma unroll
    for (int i = 0; i < NR; i++) { qh[i] = 0.f; ch[i] = 0.f; }

    float Sf = 0.f, Ss = 0.f, Sg = 0.f;
    const int base = s*NH + h;
    float pl[PD], ev[PD], vm[PD];
    #pragma unroll
    for (int j = 0; j < PD; j++) {
        int ix = j*NS*NH + base;
        pl[j] = g_Pl[ix]; ev[j] = g_Ev[ix]; vm[j] = g_vm[ix];
    }

    for (int t0 = 0; t0 < NT; t0 += PD) {
        #pragma unroll
        for (int j = 0; j < PD; j++) {
            int t = t0 + j;
            if (t >= NT) break;                 // uniform across block
            int rm = t*NS + s;
            float Psv = g_Ps[rm];
            float T1  = x[(size_t)rm*6 + 2];
            float T2  = x[(size_t)rm*6 + 3];

            float a  = Sf + Psv;
            float qf = fminf(a, vm[j]);
            Sf = fmaxf(a - vm[j], 0.f);
            float H  = fmaxf(Ss + pl[j] + qf - ev[j], 0.f);
            float qp = fmaxf(kp*(H - gL), 0.f);
            float qs = ksv * fminf(H, gL);
            Ss = H - qp - qs;
            float qso = qs*(1.f - gp);
            float qsg = qs*gp;
            float sg2 = Sg + qsg;
            float qg  = kg*sg2 + qb;
            Sg = (1.f - kg)*sg2 - qb;

            float cp = __expf(cc0 + T1*wp1 + T2*wp2);
            float cs = __expf(cc1 + T1*ws1 + T2*ws2);
            float cg = __expf(cc2 + T1*wg1 + T2*wg2);

            float QS = qp + qso + qg;
            float CS = qp*cp*0.1f + qso*cs + qg*cg;

            int tn = t + PD;
            if (tn < NT) {
                int ix = tn*NS*NH + base;
                pl[j] = g_Pl[ix]; ev[j] = g_Ev[ix]; vm[j] = g_vm[ix];
            }

            #pragma unroll
            for (int i = NR-1; i >= 1; i--) { qh[i] = qh[i-1]; ch[i] = ch[i-1]; }
            qh[0] = QS; ch[0] = CS;
            float pq = 0.f, pc = 0.f;
            #pragma unroll
            for (int i = 0; i < NR; i++) { pq += qh[i]*rg[i]; pc += ch[i]*rg[i]; }

            #pragma unroll
            for (int o = 16; o; o >>= 1) {
                pq += __shfl_down_sync(0xffffffffu, pq, o);
                pc += __shfl_down_sync(0xffffffffu, pc, o);
            }
            if (lane == 0) {
                int pix = rm*4 + warp;
                g_pq[pix] = pq;
                g_pc[pix] = pc;
            }
        }
    }
}

// ============ Kernel 4: combine per-warp partials -> outQ, outC ===================
__global__ void __launch_bounds__(256) combine_kernel(float* __restrict__ out)
{
    int idx = blockIdx.x*256 + threadIdx.x;    // idx = t*NS + s
    if (idx >= NROWS) return;
    const float4 q4 = *(const float4*)&g_pq[idx*4];
    const float4 c4 = *(const float4*)&g_pc[idx*4];
    float q = ((q4.x + q4.y) + q4.z) + q4.w;
    float c = ((c4.x + c4.y) + c4.z) + c4.w;
    out[idx]         = q;
    out[NROWS + idx] = c / q;
}

// ==================================== launch ======================================
extern "C" void kernel_launch(void* const* d_in, const int* in_sizes, int n_in,
                              void* d_out, int out_size)
{
    const float* x       = (const float*)d_in[0];
    const float* xc      = (const float*)d_in[1];
    const float* fcR_w1  = (const float*)d_in[2];
    const float* fcR_b1  = (const float*)d_in[3];
    const float* fcR_w2  = (const float*)d_in[4];
    const float* fcR_b2  = (const float*)d_in[5];
    const float* fcW_w1  = (const float*)d_in[6];
    const float* fcW_b1  = (const float*)d_in[7];
    const float* fcW_w2  = (const float*)d_in[8];
    const float* fcW_b2  = (const float*)d_in[9];
    const float* fcT_w1  = (const float*)d_in[10];
    const float* fcT_b1  = (const float*)d_in[11];
    const float* fcT_w2  = (const float*)d_in[12];
    const float* fcT_b2  = (const float*)d_in[13];
    const float* fcCT_w  = (const float*)d_in[14];
    const float* fcCT_b  = (const float*)d_in[15];
    float* out = (float*)d_out;

    site_kernel<<<NS/SB, 256>>>(xc, fcR_w1, fcR_b1, fcR_w2, fcR_b2,
                                fcW_w1, fcW_b1, fcW_w2, fcW_b2,
                                fcT_w1, fcT_b1, fcCT_w, fcCT_b);        // launch 1
    split_w_kernel<<<(NDIM*K2DIM + 255)/256, 256>>>(fcT_w2);             // launch 2
    hidden_kernel<<<NROWS, 128>>>(x, fcT_w1);                            // launch 3
    dim3 gg(3, NTILES);
    fct_mma_kernel<<<gg, 256, SM_BYTES>>>(x, fcT_b2);                    // launch 4 <- ncu capture
    scanwarp_kernel<<<NS, 128>>>(x, fcCT_w);                             // launch 5
    combine_kernel<<<(NROWS + 255)/256, 256>>>(out);                     // launch 6
}